// round 12
// baseline (speedup 1.0000x reference)
#include <cuda_runtime.h>
#include <cuda_fp16.h>
#include <cstdint>

// ---------------------------------------------------------------------------
// Problem constants
// ---------------------------------------------------------------------------
#define M_TOTAL 4096            // 4 * 1024
#define N_TOTAL 11008
#define K_TOTAL 4096
#define PACKED_LEN (N_TOTAL * K_TOTAL / 4)   // int32 elements, one byte each

#define BM 128
#define BN 128
#define BK 64                   // fp16 elems per stage = 128 bytes = SW128 atom row
#define S_STAGES (K_TOTAL / BK) // 64
#define NTHREADS 128
#define NSTAGES 3

#define M_TILES (M_TOTAL / BM)          // 32
#define N_TILES (N_TOTAL / BN)          // 86
#define NTILES  (M_TILES * N_TILES)     // 2752
#define GRID    296                     // persistent: 2 CTAs per SM

// SMEM: 3 stage buffers, each A tile 16KB + B tile 16KB
#define A_TILE_BYTES 16384
#define B_TILE_BYTES 16384
#define STAGE_BYTES  (A_TILE_BYTES + B_TILE_BYTES)         // 32768
#define SMEM_TOTAL_BYTES (NSTAGES * STAGE_BYTES)           // 98304

// Prep kernel grid split
#define CONV_BLOCKS ((M_TOTAL * K_TOTAL / 4) / 256)    // 16384
#define DEQ_BLOCKS  ((PACKED_LEN / 4) / 256)           // 11008
#define PREP_BLOCKS (CONV_BLOCKS + DEQ_BLOCKS)

// ---------------------------------------------------------------------------
// Device scratch (module-static; no runtime allocation)
// ---------------------------------------------------------------------------
__device__ __half g_A[(size_t)M_TOTAL * K_TOTAL];   // 32 MB, x in fp16
__device__ __half g_B[(size_t)N_TOTAL * K_TOTAL];   // 88 MB, dequantized W

// ---------------------------------------------------------------------------
// PTX helpers (baseline ISA only: cp.async sm_80, ldmatrix sm_75, mma sm_80)
// ---------------------------------------------------------------------------
static __device__ __forceinline__ uint32_t smem_u32(const void* p) {
    uint32_t a;
    asm("{ .reg .u64 t; cvta.to.shared.u64 t, %1; cvt.u32.u64 %0, t; }"
        : "=r"(a) : "l"(p));
    return a;
}

#define CP_ASYNC16(dst, src) \
    asm volatile("cp.async.cg.shared.global [%0], [%1], 16;" \
                 :: "r"(dst), "l"(src) : "memory")
#define CP_COMMIT() asm volatile("cp.async.commit_group;" ::: "memory")
#define CP_WAIT1()  asm volatile("cp.async.wait_group 1;" ::: "memory")
#define CP_WAIT0()  asm volatile("cp.async.wait_group 0;" ::: "memory")

#define LDMATRIX_X4(r0, r1, r2, r3, addr) \
    asm volatile("ldmatrix.sync.aligned.m8n8.x4.shared.b16 {%0,%1,%2,%3}, [%4];" \
                 : "=r"(r0), "=r"(r1), "=r"(r2), "=r"(r3) : "r"(addr))

// D = A*B + D, m16n8k16, f16 in, f32 acc
#define MMA_16816(c0, c1, c2, c3, a0, a1, a2, a3, b0, b1) \
    asm volatile("mma.sync.aligned.m16n8k16.row.col.f32.f16.f16.f32 " \
                 "{%0,%1,%2,%3}, {%4,%5,%6,%7}, {%8,%9}, {%0,%1,%2,%3};" \
                 : "+f"(c0), "+f"(c1), "+f"(c2), "+f"(c3) \
                 : "r"(a0), "r"(a1), "r"(a2), "r"(a3), "r"(b0), "r"(b1))

// Streaming store: 180MB write-once output shouldn't evict the B stream in L2
#define STG_CS_F32X2(ptr, vx, vy) \
    asm volatile("st.global.cs.v2.f32 [%0], {%1, %2};" \
                 :: "l"(ptr), "f"(vx), "f"(vy) : "memory")

// SW128 swizzle of a byte offset within a [row][128B] tile
#define SW128(off) ((off) ^ (((off) >> 3) & 0x70))

// ---------------------------------------------------------------------------
// Fused prologue: x f32->fp16 AND weight dequant (2 launches/call total so
// ncu -s 5 -c 1 lands on gemm_kernel).
// ---------------------------------------------------------------------------
static __device__ __forceinline__ uint2 dequant4(unsigned v) {
    // fp16 patterns for field-1: 0 -> -1 (0xBC00), 1 -> 0, 2 -> 1 (0x3C00), 3 -> 2 (0x4000)
    const unsigned long long LUT = 0x40003C000000BC00ull;
    unsigned h0 = (unsigned)((LUT >> (16u * (v & 3u))) & 0xFFFFu);
    unsigned h1 = (unsigned)((LUT >> (16u * ((v >> 2) & 3u))) & 0xFFFFu);
    unsigned h2 = (unsigned)((LUT >> (16u * ((v >> 4) & 3u))) & 0xFFFFu);
    unsigned h3 = (unsigned)((LUT >> (16u * ((v >> 6) & 3u))) & 0xFFFFu);
    return make_uint2(h0 | (h1 << 16), h2 | (h3 << 16));
}

__global__ void __launch_bounds__(256) prep_kernel(
    const float4* __restrict__ x, const int4* __restrict__ pw)
{
    int b = blockIdx.x;
    if (b < CONV_BLOCKS) {
        int i = b * 256 + threadIdx.x;
        float4 v = x[i];
        __half2* A2 = reinterpret_cast<__half2*>(g_A);
        A2[2 * i]     = __floats2half2_rn(v.x, v.y);
        A2[2 * i + 1] = __floats2half2_rn(v.z, v.w);
    } else {
        int i = (b - CONV_BLOCKS) * 256 + threadIdx.x;
        int4 p = pw[i];
        uint2* B2 = reinterpret_cast<uint2*>(g_B);  // 4 halves per uint2
        B2[4 * i + 0] = dequant4((unsigned)p.x);
        B2[4 * i + 1] = dequant4((unsigned)p.y);
        B2[4 * i + 2] = dequant4((unsigned)p.z);
        B2[4 * i + 3] = dequant4((unsigned)p.w);
    }
}

// ---------------------------------------------------------------------------
// Priming-only stage loader (steady-state loads are spread in the ks loop).
// ---------------------------------------------------------------------------
static __device__ __forceinline__ void load_stage_prime(
    int buf, int st, uint32_t smem_base, uint32_t swBase,
    const char* gA, const char* gB)
{
    uint32_t aB = smem_base + (uint32_t)buf * STAGE_BYTES + swBase;
    uint32_t bB = aB + A_TILE_BYTES;
    const char* As = gA + (size_t)st * (BK * 2);
    const char* Bs = gB + (size_t)st * (BK * 2);
    #pragma unroll
    for (int c = 0; c < 8; c++)
        CP_ASYNC16(aB + 2048u * c, As + (size_t)c * 16 * K_TOTAL * 2);
    #pragma unroll
    for (int c = 0; c < 8; c++)
        CP_ASYNC16(bB + 2048u * c, Bs + (size_t)c * 16 * K_TOTAL * 2);
}

// ---------------------------------------------------------------------------
// Persistent GEMM, 2 CTAs/SM: grid=296, 128x128 CTA tile, 4 warps (2Mx2N),
// warp tile 64x64, 3-stage pipeline across tiles. Per stage:
//   WAIT0 (stages s, s+1 resident -> cross-stage prefetch race-free) -> sync
//   -> ks loop: 1 LDSM prefetch + 1 cp.async (ks 0-1) + 4 MMAs per group.
// The 16 LDGSTS are SPREAD across 16 MMA groups instead of clumped at the
// barrier, so the tensor pipe never drains while both CTAs issue loads.
// ---------------------------------------------------------------------------
__global__ void __launch_bounds__(NTHREADS, 2)
gemm_kernel(const float* __restrict__ scale_p, float* __restrict__ out)
{
    extern __shared__ char smem[];
    uint32_t smem_base = smem_u32(smem);
    int tid = threadIdx.x;
    int wid = tid >> 5;
    int lid = tid & 31;

    int warp_m = (wid & 1) * 64;   // 0 or 64
    int warp_n = (wid >> 1) * 64;  // 0 or 64

    // ---- per-thread cp.async constants ----
    int ldRow = tid >> 3;          // 0..15
    int ldCol = tid & 7;
    uint32_t swBase = SW128((uint32_t)(ldRow * 128 + ldCol * 16));

    // ---- per-thread ldmatrix constants (A and B identical scheme) ----
    int mat  = lid >> 3;
    int r    = lid & 7;
    int rowA0 = warp_m + ((mat & 1) << 3) + r;
    int rowB0 = warp_n + ((mat & 1) << 3) + r;
    uint32_t cxor = (uint32_t)(((mat >> 1) << 4)) ^ ((uint32_t)r << 4);
    uint32_t arA[4], arB[4];
    #pragma unroll
    for (int mi = 0; mi < 4; mi++) arA[mi] = (uint32_t)((rowA0 + mi * 16) * 128);
    #pragma unroll
    for (int nb = 0; nb < 4; nb++) arB[nb] = (uint32_t)((rowB0 + nb * 16) * 128)
                                             + A_TILE_BYTES;

    float scale = *scale_p;

    // ---- load cursor (runs continuously across tiles) ----
    int ldTile  = blockIdx.x;
    int ldStage = 0;
    int lbuf    = 0;               // smem buffer 0..2, rotates across tiles
    const char* gAl = reinterpret_cast<const char*>(
        g_A + (size_t)((ldTile & 31) * BM + ldRow) * K_TOTAL + ldCol * 8);
    const char* gBl = reinterpret_cast<const char*>(
        g_B + (size_t)((ldTile >> 5) * BN + ldRow) * K_TOTAL + ldCol * 8);

    // Prime 2 stages (buffers 0,1)
    #pragma unroll
    for (int p = 0; p < 2; p++) {
        load_stage_prime(lbuf, ldStage, smem_base, swBase, gAl, gBl);
        CP_COMMIT();
        ldStage++;
        lbuf = (lbuf == NSTAGES - 1) ? 0 : lbuf + 1;
    }
    CP_WAIT1();                  // stage 0 resident
    __syncthreads();

    uint32_t a_frag[2][4][4];
    uint32_t b_frag[2][8][2];

    // Preload first tile, stage 0, ks 0 fragments into frag buffer 0
    {
        #pragma unroll
        for (int mi = 0; mi < 4; mi++)
            LDMATRIX_X4(a_frag[0][mi][0], a_frag[0][mi][1],
                        a_frag[0][mi][2], a_frag[0][mi][3],
                        smem_base + arA[mi] + cxor);
        #pragma unroll
        for (int nb = 0; nb < 4; nb++) {
            uint32_t r0, r1, r2, r3;
            LDMATRIX_X4(r0, r1, r2, r3, smem_base + arB[nb] + cxor);
            b_frag[0][nb * 2 + 0][0] = r0; b_frag[0][nb * 2 + 0][1] = r2;
            b_frag[0][nb * 2 + 1][0] = r1; b_frag[0][nb * 2 + 1][1] = r3;
        }
    }

    float acc[4][8][4];
    #pragma unroll
    for (int mi = 0; mi < 4; mi++)
        #pragma unroll
        for (int ni = 0; ni < 8; ni++)
            #pragma unroll
            for (int c = 0; c < 4; c++) acc[mi][ni][c] = 0.0f;

    int cbuf = 0;                  // compute buffer cursor

    for (int tile = blockIdx.x; tile < NTILES; tile += GRID) {
        int mBase = (tile & 31) * BM;
        int nBase = (tile >> 5) * BN;
        bool last_tile = (tile + GRID >= NTILES);

        for (int s = 0; s < S_STAGES; s++) {
            // Drain ALL outstanding groups: stages s and s+1 both resident.
            // (Group s+1 was committed a full stage ago -> near-zero wait.)
            CP_WAIT0();
            __syncthreads();

            // Capture stage s+2's load work (issued spread inside ks loop).
            bool do_load = (ldTile < NTILES);
            uint32_t aDst = smem_base + (uint32_t)lbuf * STAGE_BYTES + swBase;
            uint32_t bDst = aDst + A_TILE_BYTES;
            const char* As = gAl + (size_t)ldStage * (BK * 2);
            const char* Bs = gBl + (size_t)ldStage * (BK * 2);

            // Advance cursor
            lbuf = (lbuf == NSTAGES - 1) ? 0 : lbuf + 1;
            if (++ldStage == S_STAGES) {
                ldStage = 0;
                ldTile += GRID;
                if (ldTile < NTILES) {
                    gAl = reinterpret_cast<const char*>(
                        g_A + (size_t)((ldTile & 31) * BM + ldRow) * K_TOTAL + ldCol * 8);
                    gBl = reinterpret_cast<const char*>(
                        g_B + (size_t)((ldTile >> 5) * BN + ldRow) * K_TOTAL + ldCol * 8);
                }
            }

            uint32_t stageT = smem_base + (uint32_t)cbuf * STAGE_BYTES;
            int nbuf = (cbuf == NSTAGES - 1) ? 0 : cbuf + 1;
            uint32_t nextT = smem_base + (uint32_t)nbuf * STAGE_BYTES;

            #pragma unroll
            for (int ks = 0; ks < 4; ks++) {
                int cur = ks & 1;
                int nxt = cur ^ 1;

                // Fragment prefetch: ks+1 of this stage, or ks=0 of the next
                // stage (safe: WAIT0 above guaranteed stage s+1 resident).
                uint32_t pT, pkb;
                bool do_pref;
                if (ks < 3) {
                    pT = stageT; pkb = (uint32_t)((ks + 1) * 32) ^ cxor; do_pref = true;
                } else {
                    pT = nextT;
                    pkb = cxor;
                    do_pref = (s + 1 < S_STAGES) || !last_tile;
                }

                // Commit the spread LDGSTS group once all 16 are issued.
                if (ks == 2) CP_COMMIT();

                // 8 groups: [1 cp.async (ks 0-1)] + 1 LDSM + 4 MMAs each
                #pragma unroll
                for (int g = 0; g < 8; g++) {
                    if (ks == 0 && do_load)
                        CP_ASYNC16(aDst + 2048u * g,
                                   As + (size_t)g * 16 * K_TOTAL * 2);
                    if (ks == 1 && do_load)
                        CP_ASYNC16(bDst + 2048u * g,
                                   Bs + (size_t)g * 16 * K_TOTAL * 2);
                    if (do_pref) {
                        if (g < 4) {
                            LDMATRIX_X4(a_frag[nxt][g][0], a_frag[nxt][g][1],
                                        a_frag[nxt][g][2], a_frag[nxt][g][3],
                                        pT + arA[g] + pkb);
                        } else {
                            int nb = g - 4;
                            uint32_t r0, r1, r2, r3;
                            LDMATRIX_X4(r0, r1, r2, r3, pT + arB[nb] + pkb);
                            b_frag[nxt][nb * 2 + 0][0] = r0; b_frag[nxt][nb * 2 + 0][1] = r2;
                            b_frag[nxt][nb * 2 + 1][0] = r1; b_frag[nxt][nb * 2 + 1][1] = r3;
                        }
                    }
                    int mi = g & 3;
                    int nh = (g >> 2) * 4;
                    #pragma unroll
                    for (int nj = 0; nj < 4; nj++) {
                        int ni = nh + nj;
                        MMA_16816(acc[mi][ni][0], acc[mi][ni][1],
                                  acc[mi][ni][2], acc[mi][ni][3],
                                  a_frag[cur][mi][0], a_frag[cur][mi][1],
                                  a_frag[cur][mi][2], a_frag[cur][mi][3],
                                  b_frag[cur][ni][0], b_frag[cur][ni][1]);
                    }
                }
            }
            cbuf = nbuf;
        }

        // Epilogue (next tile's loads already in flight; co-resident CTA
        // keeps the tensor pipe busy meanwhile). Streaming stores.
        int erow = lid >> 2;
        int ecol = (lid & 3) * 2;
        #pragma unroll
        for (int mi = 0; mi < 4; mi++) {
            #pragma unroll
            for (int ni = 0; ni < 8; ni++) {
                int row = mBase + warp_m + mi * 16 + erow;
                int col = nBase + warp_n + ni * 8 + ecol;
                float* p0 = out + (size_t)row * N_TOTAL + col;
                float* p1 = out + (size_t)(row + 8) * N_TOTAL + col;
                STG_CS_F32X2(p0, acc[mi][ni][0] * scale, acc[mi][ni][1] * scale);
                STG_CS_F32X2(p1, acc[mi][ni][2] * scale, acc[mi][ni][3] * scale);
                acc[mi][ni][0] = 0.0f; acc[mi][ni][1] = 0.0f;
                acc[mi][ni][2] = 0.0f; acc[mi][ni][3] = 0.0f;
            }
        }
    }
}

// ---------------------------------------------------------------------------
// Harness entry
// ---------------------------------------------------------------------------
extern "C" void kernel_launch(void* const* d_in, const int* in_sizes, int n_in,
                              void* d_out, int out_size)
{
    const float* x  = (const float*)d_in[0];
    const int*   pw = (const int*)d_in[1];
    const float* ws = (const float*)d_in[2];
    float* out = (float*)d_out;

    cudaFuncSetAttribute(gemm_kernel,
                         cudaFuncAttributeMaxDynamicSharedMemorySize,
                         SMEM_TOTAL_BYTES);

    prep_kernel<<<PREP_BLOCKS, 256>>>(
        reinterpret_cast<const float4*>(x),
        reinterpret_cast<const int4*>(pw));
    gemm_kernel<<<GRID, NTHREADS, SMEM_TOTAL_BYTES>>>(ws, out);
}

// round 13
// speedup vs baseline: 1.0147x; 1.0147x over previous
#include <cuda_runtime.h>
#include <cuda_fp16.h>
#include <cstdint>

// ---------------------------------------------------------------------------
// Problem constants
// ---------------------------------------------------------------------------
#define M_TOTAL 4096            // 4 * 1024
#define N_TOTAL 11008
#define K_TOTAL 4096
#define PACKED_LEN (N_TOTAL * K_TOTAL / 4)   // int32 elements, one byte each

#define BM 128
#define BN 128
#define BK 64                   // fp16 elems per stage = 128 bytes = SW128 atom row
#define S_STAGES (K_TOTAL / BK) // 64
#define NTHREADS 128
#define NSTAGES 3

#define M_TILES (M_TOTAL / BM)          // 32
#define N_TILES (N_TOTAL / BN)          // 86
#define NTILES  (M_TILES * N_TILES)     // 2752
#define GRID    296                     // persistent: 2 CTAs per SM

// SMEM: 3 stage buffers (A 16KB + B 16KB each) + scheduler slot
#define A_TILE_BYTES 16384
#define B_TILE_BYTES 16384
#define STAGE_BYTES  (A_TILE_BYTES + B_TILE_BYTES)         // 32768
#define SCHED_SLOT   (NSTAGES * STAGE_BYTES)               // 98304
#define SMEM_TOTAL_BYTES (SCHED_SLOT + 128)                // 98432

// Prep kernel grid split
#define CONV_BLOCKS ((M_TOTAL * K_TOTAL / 4) / 256)    // 16384
#define DEQ_BLOCKS  ((PACKED_LEN / 4) / 256)           // 11008
#define PREP_BLOCKS (CONV_BLOCKS + DEQ_BLOCKS)

// ---------------------------------------------------------------------------
// Device scratch (module-static; no runtime allocation)
// ---------------------------------------------------------------------------
__device__ __half g_A[(size_t)M_TOTAL * K_TOTAL];   // 32 MB, x in fp16
__device__ __half g_B[(size_t)N_TOTAL * K_TOTAL];   // 88 MB, dequantized W
__device__ unsigned g_tileCtr;                      // dynamic tile scheduler

// ---------------------------------------------------------------------------
// PTX helpers (baseline ISA only: cp.async sm_80, ldmatrix sm_75, mma sm_80)
// ---------------------------------------------------------------------------
static __device__ __forceinline__ uint32_t smem_u32(const void* p) {
    uint32_t a;
    asm("{ .reg .u64 t; cvta.to.shared.u64 t, %1; cvt.u32.u64 %0, t; }"
        : "=r"(a) : "l"(p));
    return a;
}

#define CP_ASYNC16(dst, src) \
    asm volatile("cp.async.cg.shared.global [%0], [%1], 16;" \
                 :: "r"(dst), "l"(src) : "memory")
#define CP_COMMIT() asm volatile("cp.async.commit_group;" ::: "memory")
#define CP_WAIT1()  asm volatile("cp.async.wait_group 1;" ::: "memory")
#define CP_WAIT0()  asm volatile("cp.async.wait_group 0;" ::: "memory")

#define LDMATRIX_X4(r0, r1, r2, r3, addr) \
    asm volatile("ldmatrix.sync.aligned.m8n8.x4.shared.b16 {%0,%1,%2,%3}, [%4];" \
                 : "=r"(r0), "=r"(r1), "=r"(r2), "=r"(r3) : "r"(addr))

// D = A*B + D, m16n8k16, f16 in, f32 acc
#define MMA_16816(c0, c1, c2, c3, a0, a1, a2, a3, b0, b1) \
    asm volatile("mma.sync.aligned.m16n8k16.row.col.f32.f16.f16.f32 " \
                 "{%0,%1,%2,%3}, {%4,%5,%6,%7}, {%8,%9}, {%0,%1,%2,%3};" \
                 : "+f"(c0), "+f"(c1), "+f"(c2), "+f"(c3) \
                 : "r"(a0), "r"(a1), "r"(a2), "r"(a3), "r"(b0), "r"(b1))

// Streaming store: 180MB write-once output shouldn't evict the B stream in L2
#define STG_CS_F32X2(ptr, vx, vy) \
    asm volatile("st.global.cs.v2.f32 [%0], {%1, %2};" \
                 :: "l"(ptr), "f"(vx), "f"(vy) : "memory")

// SW128 swizzle of a byte offset within a [row][128B] tile
#define SW128(off) ((off) ^ (((off) >> 3) & 0x70))

// ---------------------------------------------------------------------------
// Fused prologue: x f32->fp16 AND weight dequant (2 launches/call total so
// ncu -s 5 -c 1 lands on gemm_kernel). Also resets the tile scheduler
// (prep precedes gemm in-stream -> replay-safe).
// ---------------------------------------------------------------------------
static __device__ __forceinline__ uint2 dequant4(unsigned v) {
    // fp16 patterns for field-1: 0 -> -1 (0xBC00), 1 -> 0, 2 -> 1 (0x3C00), 3 -> 2 (0x4000)
    const unsigned long long LUT = 0x40003C000000BC00ull;
    unsigned h0 = (unsigned)((LUT >> (16u * (v & 3u))) & 0xFFFFu);
    unsigned h1 = (unsigned)((LUT >> (16u * ((v >> 2) & 3u))) & 0xFFFFu);
    unsigned h2 = (unsigned)((LUT >> (16u * ((v >> 4) & 3u))) & 0xFFFFu);
    unsigned h3 = (unsigned)((LUT >> (16u * ((v >> 6) & 3u))) & 0xFFFFu);
    return make_uint2(h0 | (h1 << 16), h2 | (h3 << 16));
}

__global__ void __launch_bounds__(256) prep_kernel(
    const float4* __restrict__ x, const int4* __restrict__ pw)
{
    int b = blockIdx.x;
    if (b == 0 && threadIdx.x == 0) g_tileCtr = GRID;   // tiles 0..GRID-1 are bids
    if (b < CONV_BLOCKS) {
        int i = b * 256 + threadIdx.x;
        float4 v = x[i];
        __half2* A2 = reinterpret_cast<__half2*>(g_A);
        A2[2 * i]     = __floats2half2_rn(v.x, v.y);
        A2[2 * i + 1] = __floats2half2_rn(v.z, v.w);
    } else {
        int i = (b - CONV_BLOCKS) * 256 + threadIdx.x;
        int4 p = pw[i];
        uint2* B2 = reinterpret_cast<uint2*>(g_B);  // 4 halves per uint2
        B2[4 * i + 0] = dequant4((unsigned)p.x);
        B2[4 * i + 1] = dequant4((unsigned)p.y);
        B2[4 * i + 2] = dequant4((unsigned)p.z);
        B2[4 * i + 3] = dequant4((unsigned)p.w);
    }
}

// ---------------------------------------------------------------------------
// Stage loader (no commit; caller commits). 128 threads:
// A 1024 16B chunks -> 8/thread, B same. ldRow = tid>>3 (0..15); chunk c adds
// 16 rows (row%8 preserved -> swizzle bits unchanged; smem +2048c).
// ---------------------------------------------------------------------------
static __device__ __forceinline__ void load_stage(
    int buf, int st, uint32_t smem_base, uint32_t swBase,
    const char* gA, const char* gB)
{
    uint32_t aB = smem_base + (uint32_t)buf * STAGE_BYTES + swBase;
    uint32_t bB = aB + A_TILE_BYTES;
    const char* As = gA + (size_t)st * (BK * 2);
    const char* Bs = gB + (size_t)st * (BK * 2);
    #pragma unroll
    for (int c = 0; c < 8; c++)
        CP_ASYNC16(aB + 2048u * c, As + (size_t)c * 16 * K_TOTAL * 2);
    #pragma unroll
    for (int c = 0; c < 8; c++)
        CP_ASYNC16(bB + 2048u * c, Bs + (size_t)c * 16 * K_TOTAL * 2);
}

// ---------------------------------------------------------------------------
// Persistent GEMM, 2 CTAs/SM, DYNAMIC tile scheduler: each CTA starts at
// tile=bid; at each tile's start tid0 fetches the next tile id via atomicAdd
// (broadcast through smem, published by the stage-0 barrier). Removes the
// 10-vs-9 tile static imbalance (88 CTAs did 11% more work).
// 128x128 CTA tile, 4 warps (2Mx2N), warp tile 64x64, 3-stage pipeline
// across tiles, WAIT0 ordering (race-free cross-stage fragment prefetch),
// LDSM interleaved with MMA groups (round-11 structure).
// ---------------------------------------------------------------------------
__global__ void __launch_bounds__(NTHREADS, 2)
gemm_kernel(const float* __restrict__ scale_p, float* __restrict__ out)
{
    extern __shared__ char smem[];
    uint32_t smem_base = smem_u32(smem);
    int tid = threadIdx.x;
    int wid = tid >> 5;
    int lid = tid & 31;

    int warp_m = (wid & 1) * 64;   // 0 or 64
    int warp_n = (wid >> 1) * 64;  // 0 or 64

    // ---- per-thread cp.async constants ----
    int ldRow = tid >> 3;          // 0..15
    int ldCol = tid & 7;
    uint32_t swBase = SW128((uint32_t)(ldRow * 128 + ldCol * 16));

    // ---- per-thread ldmatrix constants (A and B identical scheme) ----
    int mat  = lid >> 3;
    int r    = lid & 7;
    int rowA0 = warp_m + ((mat & 1) << 3) + r;
    int rowB0 = warp_n + ((mat & 1) << 3) + r;
    uint32_t cxor = (uint32_t)(((mat >> 1) << 4)) ^ ((uint32_t)r << 4);
    uint32_t arA[4], arB[4];
    #pragma unroll
    for (int mi = 0; mi < 4; mi++) arA[mi] = (uint32_t)((rowA0 + mi * 16) * 128);
    #pragma unroll
    for (int nb = 0; nb < 4; nb++) arB[nb] = (uint32_t)((rowB0 + nb * 16) * 128)
                                             + A_TILE_BYTES;

    float scale = *scale_p;
    uint32_t schedSlot = smem_base + SCHED_SLOT;

    // ---- load cursor (runs continuously across tiles) ----
    int ldTile  = blockIdx.x;
    int ldStage = 0;
    int lbuf    = 0;               // smem buffer 0..2, rotates across tiles
    const char* gAl = reinterpret_cast<const char*>(
        g_A + (size_t)((ldTile & 31) * BM + ldRow) * K_TOTAL + ldCol * 8);
    const char* gBl = reinterpret_cast<const char*>(
        g_B + (size_t)((ldTile >> 5) * BN + ldRow) * K_TOTAL + ldCol * 8);

    // Prime 2 stages (buffers 0,1)
    #pragma unroll
    for (int p = 0; p < 2; p++) {
        load_stage(lbuf, ldStage, smem_base, swBase, gAl, gBl);
        CP_COMMIT();
        ldStage++;
        lbuf = (lbuf == NSTAGES - 1) ? 0 : lbuf + 1;
    }
    CP_WAIT1();                  // stage 0 resident
    __syncthreads();

    uint32_t a_frag[2][4][4];
    uint32_t b_frag[2][8][2];

    // Preload first tile, stage 0, ks 0 fragments into frag buffer 0
    {
        #pragma unroll
        for (int mi = 0; mi < 4; mi++)
            LDMATRIX_X4(a_frag[0][mi][0], a_frag[0][mi][1],
                        a_frag[0][mi][2], a_frag[0][mi][3],
                        smem_base + arA[mi] + cxor);
        #pragma unroll
        for (int nb = 0; nb < 4; nb++) {
            uint32_t r0, r1, r2, r3;
            LDMATRIX_X4(r0, r1, r2, r3, smem_base + arB[nb] + cxor);
            b_frag[0][nb * 2 + 0][0] = r0; b_frag[0][nb * 2 + 0][1] = r2;
            b_frag[0][nb * 2 + 1][0] = r1; b_frag[0][nb * 2 + 1][1] = r3;
        }
    }

    float acc[4][8][4];
    #pragma unroll
    for (int mi = 0; mi < 4; mi++)
        #pragma unroll
        for (int ni = 0; ni < 8; ni++)
            #pragma unroll
            for (int c = 0; c < 4; c++) acc[mi][ni][c] = 0.0f;

    int cbuf = 0;                  // compute buffer cursor
    int tile = blockIdx.x;

    while (tile < NTILES) {
        int mBase = (tile & 31) * BM;
        int nBase = (tile >> 5) * BN;

        // Fetch the NEXT tile id (consumed by the load cursor ~62 stages
        // later and by the tile loop after the epilogue).
        if (tid == 0) {
            unsigned nx = atomicAdd(&g_tileCtr, 1u);
            asm volatile("st.shared.u32 [%0], %1;" :: "r"(schedSlot), "r"(nx)
                         : "memory");
        }
        int nxtTile = 0;

        for (int s = 0; s < S_STAGES; s++) {
            // Drain ALL outstanding groups: stages s and s+1 both resident.
            // (Group s+1 was committed a full stage ago -> near-zero wait.)
            CP_WAIT0();
            __syncthreads();       // also publishes schedSlot at s==0
            if (s == 0) {
                uint32_t nx;
                asm volatile("ld.shared.u32 %0, [%1];" : "=r"(nx)
                             : "r"(schedSlot));
                nxtTile = (int)nx;
            }

            // Issue loads for stage s+2; empty commit at tail is harmless.
            if (ldTile < NTILES)
                load_stage(lbuf, ldStage, smem_base, swBase, gAl, gBl);
            CP_COMMIT();
            lbuf = (lbuf == NSTAGES - 1) ? 0 : lbuf + 1;
            if (++ldStage == S_STAGES) {
                ldStage = 0;
                ldTile = nxtTile;          // cursor crosses into next tile
                if (ldTile < NTILES) {
                    gAl = reinterpret_cast<const char*>(
                        g_A + (size_t)((ldTile & 31) * BM + ldRow) * K_TOTAL + ldCol * 8);
                    gBl = reinterpret_cast<const char*>(
                        g_B + (size_t)((ldTile >> 5) * BN + ldRow) * K_TOTAL + ldCol * 8);
                }
            }

            uint32_t stageT = smem_base + (uint32_t)cbuf * STAGE_BYTES;
            int nbuf = (cbuf == NSTAGES - 1) ? 0 : cbuf + 1;
            uint32_t nextT = smem_base + (uint32_t)nbuf * STAGE_BYTES;

            #pragma unroll
            for (int ks = 0; ks < 4; ks++) {
                int cur = ks & 1;
                int nxt = cur ^ 1;

                // Prefetch: ks+1 of this stage, or ks=0 of the next stage
                // (possibly the next tile's stage 0 -- same buffer rotation).
                // Safe: WAIT0 above guaranteed stage s+1 resident.
                uint32_t pT, pkb;
                bool do_pref;
                if (ks < 3) {
                    pT = stageT; pkb = (uint32_t)((ks + 1) * 32) ^ cxor; do_pref = true;
                } else {
                    pT = nextT;
                    pkb = cxor;
                    do_pref = (s + 1 < S_STAGES) || (nxtTile < NTILES);
                }

                // 8 groups: 1 interleaved LDSM + 4 MMAs each
                #pragma unroll
                for (int g = 0; g < 8; g++) {
                    if (do_pref) {
                        if (g < 4) {
                            LDMATRIX_X4(a_frag[nxt][g][0], a_frag[nxt][g][1],
                                        a_frag[nxt][g][2], a_frag[nxt][g][3],
                                        pT + arA[g] + pkb);
                        } else {
                            int nb = g - 4;
                            uint32_t r0, r1, r2, r3;
                            LDMATRIX_X4(r0, r1, r2, r3, pT + arB[nb] + pkb);
                            b_frag[nxt][nb * 2 + 0][0] = r0; b_frag[nxt][nb * 2 + 0][1] = r2;
                            b_frag[nxt][nb * 2 + 1][0] = r1; b_frag[nxt][nb * 2 + 1][1] = r3;
                        }
                    }
                    int mi = g & 3;
                    int nh = (g >> 2) * 4;
                    #pragma unroll
                    for (int nj = 0; nj < 4; nj++) {
                        int ni = nh + nj;
                        MMA_16816(acc[mi][ni][0], acc[mi][ni][1],
                                  acc[mi][ni][2], acc[mi][ni][3],
                                  a_frag[cur][mi][0], a_frag[cur][mi][1],
                                  a_frag[cur][mi][2], a_frag[cur][mi][3],
                                  b_frag[cur][ni][0], b_frag[cur][ni][1]);
                    }
                }
            }
            cbuf = nbuf;
        }

        // Epilogue (next tile's loads already in flight; co-resident CTA
        // keeps the tensor pipe busy meanwhile). Streaming stores.
        int erow = lid >> 2;
        int ecol = (lid & 3) * 2;
        #pragma unroll
        for (int mi = 0; mi < 4; mi++) {
            #pragma unroll
            for (int ni = 0; ni < 8; ni++) {
                int row = mBase + warp_m + mi * 16 + erow;
                int col = nBase + warp_n + ni * 8 + ecol;
                float* p0 = out + (size_t)row * N_TOTAL + col;
                float* p1 = out + (size_t)(row + 8) * N_TOTAL + col;
                STG_CS_F32X2(p0, acc[mi][ni][0] * scale, acc[mi][ni][1] * scale);
                STG_CS_F32X2(p1, acc[mi][ni][2] * scale, acc[mi][ni][3] * scale);
                acc[mi][ni][0] = 0.0f; acc[mi][ni][1] = 0.0f;
                acc[mi][ni][2] = 0.0f; acc[mi][ni][3] = 0.0f;
            }
        }

        tile = nxtTile;
    }
}

// ---------------------------------------------------------------------------
// Harness entry
// ---------------------------------------------------------------------------
extern "C" void kernel_launch(void* const* d_in, const int* in_sizes, int n_in,
                              void* d_out, int out_size)
{
    const float* x  = (const float*)d_in[0];
    const int*   pw = (const int*)d_in[1];
    const float* ws = (const float*)d_in[2];
    float* out = (float*)d_out;

    cudaFuncSetAttribute(gemm_kernel,
                         cudaFuncAttributeMaxDynamicSharedMemorySize,
                         SMEM_TOTAL_BYTES);

    prep_kernel<<<PREP_BLOCKS, 256>>>(
        reinterpret_cast<const float4*>(x),
        reinterpret_cast<const int4*>(pw));
    gemm_kernel<<<GRID, NTHREADS, SMEM_TOTAL_BYTES>>>(ws, out);
}

// round 15
// speedup vs baseline: 1.0380x; 1.0229x over previous
#include <cuda_runtime.h>
#include <cuda_fp16.h>
#include <cstdint>

// ---------------------------------------------------------------------------
// Problem constants
// ---------------------------------------------------------------------------
#define M_TOTAL 4096            // 4 * 1024
#define N_TOTAL 11008
#define K_TOTAL 4096
#define PACKED_LEN (N_TOTAL * K_TOTAL / 4)   // int32 elements, one byte each

#define BM 128
#define BN 128
#define BK 64                   // fp16 elems per stage = 128 bytes = SW128 atom row
#define S_STAGES (K_TOTAL / BK) // 64
#define NTHREADS 128
#define NSTAGES 3

#define M_TILES (M_TOTAL / BM)          // 32
#define N_TILES (N_TOTAL / BN)          // 86
#define NTILES  (M_TILES * N_TILES)     // 2752
#define GRID    296                     // persistent: 2 CTAs per SM

// SMEM: 3 stage buffers (A 16KB + B 16KB each) + scheduler slot
#define A_TILE_BYTES 16384
#define B_TILE_BYTES 16384
#define STAGE_BYTES  (A_TILE_BYTES + B_TILE_BYTES)         // 32768
#define SCHED_SLOT   (NSTAGES * STAGE_BYTES)               // 98304
#define SMEM_TOTAL_BYTES (SCHED_SLOT + 128)                // 98432

// Prep kernel grid split (vectorized: 16B transactions both sides)
#define CONV_BLOCKS ((M_TOTAL * K_TOTAL / 8) / 256)    // 8192  (8 floats/thread)
#define DEQ_BLOCKS  ((PACKED_LEN / 4) / 256)           // 11008 (1 int4/thread)
#define PREP_BLOCKS (CONV_BLOCKS + DEQ_BLOCKS)

// ---------------------------------------------------------------------------
// Device scratch (module-static; no runtime allocation)
// ---------------------------------------------------------------------------
__device__ __half g_A[(size_t)M_TOTAL * K_TOTAL];   // 32 MB, x in fp16
__device__ __half g_B[(size_t)N_TOTAL * K_TOTAL];   // 88 MB, dequantized W
__device__ unsigned g_tileCtr;                      // dynamic tile scheduler

// ---------------------------------------------------------------------------
// PTX helpers (baseline ISA only: cp.async sm_80, ldmatrix sm_75, mma sm_80)
// ---------------------------------------------------------------------------
static __device__ __forceinline__ uint32_t smem_u32(const void* p) {
    uint32_t a;
    asm("{ .reg .u64 t; cvta.to.shared.u64 t, %1; cvt.u32.u64 %0, t; }"
        : "=r"(a) : "l"(p));
    return a;
}

#define CP_ASYNC16(dst, src) \
    asm volatile("cp.async.cg.shared.global [%0], [%1], 16;" \
                 :: "r"(dst), "l"(src) : "memory")
#define CP_COMMIT() asm volatile("cp.async.commit_group;" ::: "memory")
#define CP_WAIT1()  asm volatile("cp.async.wait_group 1;" ::: "memory")
#define CP_WAIT0()  asm volatile("cp.async.wait_group 0;" ::: "memory")

#define LDMATRIX_X4(r0, r1, r2, r3, addr) \
    asm volatile("ldmatrix.sync.aligned.m8n8.x4.shared.b16 {%0,%1,%2,%3}, [%4];" \
                 : "=r"(r0), "=r"(r1), "=r"(r2), "=r"(r3) : "r"(addr))

// D = A*B + D, m16n8k16, f16 in, f32 acc
#define MMA_16816(c0, c1, c2, c3, a0, a1, a2, a3, b0, b1) \
    asm volatile("mma.sync.aligned.m16n8k16.row.col.f32.f16.f16.f32 " \
                 "{%0,%1,%2,%3}, {%4,%5,%6,%7}, {%8,%9}, {%0,%1,%2,%3};" \
                 : "+f"(c0), "+f"(c1), "+f"(c2), "+f"(c3) \
                 : "r"(a0), "r"(a1), "r"(a2), "r"(a3), "r"(b0), "r"(b1))

// Streaming store: 180MB write-once output shouldn't evict the B stream in L2
#define STG_CS_F32X2(ptr, vx, vy) \
    asm volatile("st.global.cs.v2.f32 [%0], {%1, %2};" \
                 :: "l"(ptr), "f"(vx), "f"(vy) : "memory")

// SW128 swizzle of a byte offset within a [row][128B] tile
#define SW128(off) ((off) ^ (((off) >> 3) & 0x70))

// ---------------------------------------------------------------------------
// Fused prologue: x f32->fp16 AND weight dequant, fully 16B-vectorized
// (2 launches/call total so ncu -s 5 -c 1 lands on gemm_kernel).
// Also resets the tile scheduler (prep precedes gemm in-stream -> replay-safe).
// ---------------------------------------------------------------------------
static __device__ __forceinline__ uint2 dequant4(unsigned v) {
    // fp16 patterns for field-1: 0 -> -1 (0xBC00), 1 -> 0, 2 -> 1 (0x3C00), 3 -> 2 (0x4000)
    const unsigned long long LUT = 0x40003C000000BC00ull;
    unsigned h0 = (unsigned)((LUT >> (16u * (v & 3u))) & 0xFFFFu);
    unsigned h1 = (unsigned)((LUT >> (16u * ((v >> 2) & 3u))) & 0xFFFFu);
    unsigned h2 = (unsigned)((LUT >> (16u * ((v >> 4) & 3u))) & 0xFFFFu);
    unsigned h3 = (unsigned)((LUT >> (16u * ((v >> 6) & 3u))) & 0xFFFFu);
    return make_uint2(h0 | (h1 << 16), h2 | (h3 << 16));
}

static __device__ __forceinline__ uint32_t h2_bits(float a, float b) {
    __half2_raw r = __half2_raw(__floats2half2_rn(a, b));
    return (uint32_t)r.x | ((uint32_t)r.y << 16);
}

__global__ void __launch_bounds__(256) prep_kernel(
    const float4* __restrict__ x, const int4* __restrict__ pw)
{
    int b = blockIdx.x;
    if (b == 0 && threadIdx.x == 0) g_tileCtr = GRID;   // tiles 0..GRID-1 are bids
    if (b < CONV_BLOCKS) {
        int i = b * 256 + threadIdx.x;      // one uint4 (8 halves) per thread
        float4 v0 = x[2 * i];
        float4 v1 = x[2 * i + 1];
        uint4 o;
        o.x = h2_bits(v0.x, v0.y);
        o.y = h2_bits(v0.z, v0.w);
        o.z = h2_bits(v1.x, v1.y);
        o.w = h2_bits(v1.z, v1.w);
        reinterpret_cast<uint4*>(g_A)[i] = o;
    } else {
        int i = (b - CONV_BLOCKS) * 256 + threadIdx.x;  // one int4 per thread
        int4 p = pw[i];
        uint2 d0 = dequant4((unsigned)p.x);
        uint2 d1 = dequant4((unsigned)p.y);
        uint2 d2 = dequant4((unsigned)p.z);
        uint2 d3 = dequant4((unsigned)p.w);
        uint4 w0, w1;
        w0.x = d0.x; w0.y = d0.y; w0.z = d1.x; w0.w = d1.y;
        w1.x = d2.x; w1.y = d2.y; w1.z = d3.x; w1.w = d3.y;
        uint4* B4 = reinterpret_cast<uint4*>(g_B);
        B4[2 * i]     = w0;
        B4[2 * i + 1] = w1;
    }
}

// ---------------------------------------------------------------------------
// Stage loader (no commit; caller commits). 128 threads:
// A 1024 16B chunks -> 8/thread, B same. ldRow = tid>>3 (0..15); chunk c adds
// 16 rows (row%8 preserved -> swizzle bits unchanged; smem +2048c).
// ---------------------------------------------------------------------------
static __device__ __forceinline__ void load_stage(
    int buf, int st, uint32_t smem_base, uint32_t swBase,
    const char* gA, const char* gB)
{
    uint32_t aB = smem_base + (uint32_t)buf * STAGE_BYTES + swBase;
    uint32_t bB = aB + A_TILE_BYTES;
    const char* As = gA + (size_t)st * (BK * 2);
    const char* Bs = gB + (size_t)st * (BK * 2);
    #pragma unroll
    for (int c = 0; c < 8; c++)
        CP_ASYNC16(aB + 2048u * c, As + (size_t)c * 16 * K_TOTAL * 2);
    #pragma unroll
    for (int c = 0; c < 8; c++)
        CP_ASYNC16(bB + 2048u * c, Bs + (size_t)c * 16 * K_TOTAL * 2);
}

// ---------------------------------------------------------------------------
// Persistent GEMM, 2 CTAs/SM, DYNAMIC tile scheduler (round-13 structure,
// unchanged): 128x128 CTA tile, 4 warps (2Mx2N), warp tile 64x64, 3-stage
// pipeline across tiles, WAIT0 ordering (race-free cross-stage fragment
// prefetch), LDSM interleaved with MMA groups, streaming-store epilogue.
// ---------------------------------------------------------------------------
__global__ void __launch_bounds__(NTHREADS, 2)
gemm_kernel(const float* __restrict__ scale_p, float* __restrict__ out)
{
    extern __shared__ char smem[];
    uint32_t smem_base = smem_u32(smem);
    int tid = threadIdx.x;
    int wid = tid >> 5;
    int lid = tid & 31;

    int warp_m = (wid & 1) * 64;   // 0 or 64
    int warp_n = (wid >> 1) * 64;  // 0 or 64

    // ---- per-thread cp.async constants ----
    int ldRow = tid >> 3;          // 0..15
    int ldCol = tid & 7;
    uint32_t swBase = SW128((uint32_t)(ldRow * 128 + ldCol * 16));

    // ---- per-thread ldmatrix constants (A and B identical scheme) ----
    int mat  = lid >> 3;
    int r    = lid & 7;
    int rowA0 = warp_m + ((mat & 1) << 3) + r;
    int rowB0 = warp_n + ((mat & 1) << 3) + r;
    uint32_t cxor = (uint32_t)(((mat >> 1) << 4)) ^ ((uint32_t)r << 4);
    uint32_t arA[4], arB[4];
    #pragma unroll
    for (int mi = 0; mi < 4; mi++) arA[mi] = (uint32_t)((rowA0 + mi * 16) * 128);
    #pragma unroll
    for (int nb = 0; nb < 4; nb++) arB[nb] = (uint32_t)((rowB0 + nb * 16) * 128)
                                             + A_TILE_BYTES;

    float scale = *scale_p;
    uint32_t schedSlot = smem_base + SCHED_SLOT;

    // ---- load cursor (runs continuously across tiles) ----
    int ldTile  = blockIdx.x;
    int ldStage = 0;
    int lbuf    = 0;               // smem buffer 0..2, rotates across tiles
    const char* gAl = reinterpret_cast<const char*>(
        g_A + (size_t)((ldTile & 31) * BM + ldRow) * K_TOTAL + ldCol * 8);
    const char* gBl = reinterpret_cast<const char*>(
        g_B + (size_t)((ldTile >> 5) * BN + ldRow) * K_TOTAL + ldCol * 8);

    // Prime 2 stages (buffers 0,1)
    #pragma unroll
    for (int p = 0; p < 2; p++) {
        load_stage(lbuf, ldStage, smem_base, swBase, gAl, gBl);
        CP_COMMIT();
        ldStage++;
        lbuf = (lbuf == NSTAGES - 1) ? 0 : lbuf + 1;
    }
    CP_WAIT1();                  // stage 0 resident
    __syncthreads();

    uint32_t a_frag[2][4][4];
    uint32_t b_frag[2][8][2];

    // Preload first tile, stage 0, ks 0 fragments into frag buffer 0
    {
        #pragma unroll
        for (int mi = 0; mi < 4; mi++)
            LDMATRIX_X4(a_frag[0][mi][0], a_frag[0][mi][1],
                        a_frag[0][mi][2], a_frag[0][mi][3],
                        smem_base + arA[mi] + cxor);
        #pragma unroll
        for (int nb = 0; nb < 4; nb++) {
            uint32_t r0, r1, r2, r3;
            LDMATRIX_X4(r0, r1, r2, r3, smem_base + arB[nb] + cxor);
            b_frag[0][nb * 2 + 0][0] = r0; b_frag[0][nb * 2 + 0][1] = r2;
            b_frag[0][nb * 2 + 1][0] = r1; b_frag[0][nb * 2 + 1][1] = r3;
        }
    }

    float acc[4][8][4];
    #pragma unroll
    for (int mi = 0; mi < 4; mi++)
        #pragma unroll
        for (int ni = 0; ni < 8; ni++)
            #pragma unroll
            for (int c = 0; c < 4; c++) acc[mi][ni][c] = 0.0f;

    int cbuf = 0;                  // compute buffer cursor
    int tile = blockIdx.x;

    while (tile < NTILES) {
        int mBase = (tile & 31) * BM;
        int nBase = (tile >> 5) * BN;

        // Fetch the NEXT tile id (consumed by the load cursor ~62 stages
        // later and by the tile loop after the epilogue).
        if (tid == 0) {
            unsigned nx = atomicAdd(&g_tileCtr, 1u);
            asm volatile("st.shared.u32 [%0], %1;" :: "r"(schedSlot), "r"(nx)
                         : "memory");
        }
        int nxtTile = 0;

        for (int s = 0; s < S_STAGES; s++) {
            // Drain ALL outstanding groups: stages s and s+1 both resident.
            // (Group s+1 was committed a full stage ago -> near-zero wait.)
            CP_WAIT0();
            __syncthreads();       // also publishes schedSlot at s==0
            if (s == 0) {
                uint32_t nx;
                asm volatile("ld.shared.u32 %0, [%1];" : "=r"(nx)
                             : "r"(schedSlot));
                nxtTile = (int)nx;
            }

            // Issue loads for stage s+2; empty commit at tail is harmless.
            if (ldTile < NTILES)
                load_stage(lbuf, ldStage, smem_base, swBase, gAl, gBl);
            CP_COMMIT();
            lbuf = (lbuf == NSTAGES - 1) ? 0 : lbuf + 1;
            if (++ldStage == S_STAGES) {
                ldStage = 0;
                ldTile = nxtTile;          // cursor crosses into next tile
                if (ldTile < NTILES) {
                    gAl = reinterpret_cast<const char*>(
                        g_A + (size_t)((ldTile & 31) * BM + ldRow) * K_TOTAL + ldCol * 8);
                    gBl = reinterpret_cast<const char*>(
                        g_B + (size_t)((ldTile >> 5) * BN + ldRow) * K_TOTAL + ldCol * 8);
                }
            }

            uint32_t stageT = smem_base + (uint32_t)cbuf * STAGE_BYTES;
            int nbuf = (cbuf == NSTAGES - 1) ? 0 : cbuf + 1;
            uint32_t nextT = smem_base + (uint32_t)nbuf * STAGE_BYTES;

            #pragma unroll
            for (int ks = 0; ks < 4; ks++) {
                int cur = ks & 1;
                int nxt = cur ^ 1;

                // Prefetch: ks+1 of this stage, or ks=0 of the next stage
                // (possibly the next tile's stage 0 -- same buffer rotation).
                // Safe: WAIT0 above guaranteed stage s+1 resident.
                uint32_t pT, pkb;
                bool do_pref;
                if (ks < 3) {
                    pT = stageT; pkb = (uint32_t)((ks + 1) * 32) ^ cxor; do_pref = true;
                } else {
                    pT = nextT;
                    pkb = cxor;
                    do_pref = (s + 1 < S_STAGES) || (nxtTile < NTILES);
                }

                // 8 groups: 1 interleaved LDSM + 4 MMAs each
                #pragma unroll
                for (int g = 0; g < 8; g++) {
                    if (do_pref) {
                        if (g < 4) {
                            LDMATRIX_X4(a_frag[nxt][g][0], a_frag[nxt][g][1],
                                        a_frag[nxt][g][2], a_frag[nxt][g][3],
                                        pT + arA[g] + pkb);
                        } else {
                            int nb = g - 4;
                            uint32_t r0, r1, r2, r3;
                            LDMATRIX_X4(r0, r1, r2, r3, pT + arB[nb] + pkb);
                            b_frag[nxt][nb * 2 + 0][0] = r0; b_frag[nxt][nb * 2 + 0][1] = r2;
                            b_frag[nxt][nb * 2 + 1][0] = r1; b_frag[nxt][nb * 2 + 1][1] = r3;
                        }
                    }
                    int mi = g & 3;
                    int nh = (g >> 2) * 4;
                    #pragma unroll
                    for (int nj = 0; nj < 4; nj++) {
                        int ni = nh + nj;
                        MMA_16816(acc[mi][ni][0], acc[mi][ni][1],
                                  acc[mi][ni][2], acc[mi][ni][3],
                                  a_frag[cur][mi][0], a_frag[cur][mi][1],
                                  a_frag[cur][mi][2], a_frag[cur][mi][3],
                                  b_frag[cur][ni][0], b_frag[cur][ni][1]);
                    }
                }
            }
            cbuf = nbuf;
        }

        // Epilogue (next tile's loads already in flight; co-resident CTA
        // keeps the tensor pipe busy meanwhile). Streaming stores.
        int erow = lid >> 2;
        int ecol = (lid & 3) * 2;
        #pragma unroll
        for (int mi = 0; mi < 4; mi++) {
            #pragma unroll
            for (int ni = 0; ni < 8; ni++) {
                int row = mBase + warp_m + mi * 16 + erow;
                int col = nBase + warp_n + ni * 8 + ecol;
                float* p0 = out + (size_t)row * N_TOTAL + col;
                float* p1 = out + (size_t)(row + 8) * N_TOTAL + col;
                STG_CS_F32X2(p0, acc[mi][ni][0] * scale, acc[mi][ni][1] * scale);
                STG_CS_F32X2(p1, acc[mi][ni][2] * scale, acc[mi][ni][3] * scale);
                acc[mi][ni][0] = 0.0f; acc[mi][ni][1] = 0.0f;
                acc[mi][ni][2] = 0.0f; acc[mi][ni][3] = 0.0f;
            }
        }

        tile = nxtTile;
    }
}

// ---------------------------------------------------------------------------
// Harness entry
// ---------------------------------------------------------------------------
extern "C" void kernel_launch(void* const* d_in, const int* in_sizes, int n_in,
                              void* d_out, int out_size)
{
    const float* x  = (const float*)d_in[0];
    const int*   pw = (const int*)d_in[1];
    const float* ws = (const float*)d_in[2];
    float* out = (float*)d_out;

    cudaFuncSetAttribute(gemm_kernel,
                         cudaFuncAttributeMaxDynamicSharedMemorySize,
                         SMEM_TOTAL_BYTES);

    prep_kernel<<<PREP_BLOCKS, 256>>>(
        reinterpret_cast<const float4*>(x),
        reinterpret_cast<const int4*>(pw));
    gemm_kernel<<<GRID, NTHREADS, SMEM_TOTAL_BYTES>>>(ws, out);
}